// round 2
// baseline (speedup 1.0000x reference)
#include <cuda_runtime.h>
#include <math_constants.h>

#define BATCH 512
#define DIM   256
#define HID   512
#define NC    32      // NUM_COEFF
#define NTAIL 30      // NUM_COEFF - 2
#define NP    64      // Chebyshev points
#define TEV   16
#define MAXIT 10
#define TOLF  0.01f

#define MROWS (BATCH*NP)          // 32768
#define BSZ   (BATCH*DIM*NTAIL)   // 3,932,160
#define TRAJ_N (TEV*BATCH*DIM)    // 2,097,152
#define DELTA_OFF (TEV + TRAJ_N)  // 2,097,168
#define B_OFF (DELTA_OFF + 1)     // 2,097,169

// ---------------- scratch (device globals; no allocation allowed) ----------
__device__ float g_B[2][BSZ];                 // Picard coefficient ping-pong
__device__ float g_yg[BATCH*NP*DIM];          // y_grid  [b,p,d]
__device__ float g_h [BATCH*NP*HID];          // hidden  [b,p,h]
__device__ float g_f [BATCH*NP*DIM];          // fapprox [b,p,d]
__device__ float g_yf2[BATCH*DIM*2];
__device__ float g_h0[BATCH*HID];
__device__ float g_fi[BATCH*DIM];
__device__ float g_bsum[BATCH];

// small fp32 operators
__device__ float g_Phi[NC*NP];
__device__ float g_tcheb[NP];
__device__ float g_PD2[NTAIL*2];
__device__ float g_inv0[4];
__device__ float g_PhibTQ[NP*NTAIL];
__device__ float g_M2[2*NTAIL];
__device__ float g_PhiOut[NC*TEV];
__device__ float g_delta;
__device__ int   g_done;

// double precompute workspace
__device__ double gd_tcheb[NP];
__device__ double gd_Dt[NP];
__device__ double gd_Phi[NC*NP];
__device__ double gd_DPhi[NC*NP];
__device__ double gd_C[2*NP];
__device__ double gd_Phib[NTAIL*NP];
__device__ double gd_G[NTAIL*60];       // augmented [G | I]
__device__ double gd_PhibTQ[NP*NTAIL];

#define DPI 3.14159265358979323846

// ---------------- precompute spectral operators (1 block) ------------------
__global__ void k_precompute(const float* __restrict__ t_eval, int tn) {
    int tid = threadIdx.x;
    double t0 = (double)t_eval[0];
    double t1 = (double)t_eval[tn-1];
    double dtt = t1 - t0;
    double sg = (dtt > 0.0) ? 1.0 : ((dtt < 0.0) ? -1.0 : 0.0);
    double s = 2.0 / dtt;

    if (tid < NP) {
        double tc = -sg * cos(DPI * (double)tid / (double)NP);
        gd_tcheb[tid] = tc;
        g_tcheb[tid] = (float)tc;
        // T recurrence
        double Tm2 = 1.0, Tm1 = tc;
        gd_Phi[0*NP+tid] = 1.0;
        gd_Phi[1*NP+tid] = tc;
        #pragma unroll
        for (int n = 2; n < NC; n++) {
            double Tn = 2.0*tc*Tm1 - Tm2;
            gd_Phi[n*NP+tid] = Tn; Tm2 = Tm1; Tm1 = Tn;
        }
        // DT_k = k * U_{k-1};  DPhi = (2/(t1-t0)) * DT
        double Um1 = 1.0, U = 2.0*tc;   // U_0, U_1
        gd_DPhi[0*NP+tid] = 0.0;
        gd_DPhi[1*NP+tid] = s * 1.0 * Um1;
        gd_DPhi[2*NP+tid] = s * 2.0 * U;
        #pragma unroll
        for (int k = 3; k < NC; k++) {
            double Un = 2.0*tc*U - Um1;
            Um1 = U; U = Un;
            gd_DPhi[k*NP+tid] = s * (double)k * U;
        }
    }
    __syncthreads();
    if (tid < NP)
        gd_Dt[tid] = (tid < NP-1) ? (gd_tcheb[tid+1] - gd_tcheb[tid])
                                  : (1.0 - gd_tcheb[NP-1]);

    __shared__ double sinv0[4];
    if (tid == 0) {
        // A = [[Phi[0,0], DPhi[0,0]],[Phi[1,0], DPhi[1,0]]]; inv0 = A^-1
        double a = gd_Phi[0], b = gd_DPhi[0];
        double c = gd_Phi[1*NP], d = gd_DPhi[1*NP];
        double det = a*d - b*c;
        sinv0[0] =  d/det; sinv0[1] = -b/det;
        sinv0[2] = -c/det; sinv0[3] =  a/det;
        g_inv0[0]=(float)sinv0[0]; g_inv0[1]=(float)sinv0[1];
        g_inv0[2]=(float)sinv0[2]; g_inv0[3]=(float)sinv0[3];
        g_done = 0;
        g_delta = CUDART_INF_F;
    }
    __syncthreads();
    // C = inv0 @ D01   [2, NP]
    if (tid < 2*NP) {
        int k = tid / NP, p = tid % NP;
        gd_C[k*NP+p] = sinv0[k*2+0]*gd_DPhi[0*NP+p] + sinv0[k*2+1]*gd_DPhi[1*NP+p];
    }
    if (tid < NTAIL) {
        g_PD2[tid*2+0] = (float)gd_Phi [(tid+2)*NP + 0];
        g_PD2[tid*2+1] = (float)gd_DPhi[(tid+2)*NP + 0];
    }
    __syncthreads();
    // Phi_b[j][p] = DPhi[j+2][p] - PD2[j,0]*C[0][p] - PD2[j,1]*C[1][p]
    for (int idx = tid; idx < NTAIL*NP; idx += blockDim.x) {
        int j = idx / NP, p = idx % NP;
        double pd0 = gd_Phi [(j+2)*NP + 0];
        double pd1 = gd_DPhi[(j+2)*NP + 0];
        gd_Phib[idx] = gd_DPhi[(j+2)*NP + p] - pd0*gd_C[0*NP+p] - pd1*gd_C[1*NP+p];
    }
    __syncthreads();
    // G = Phi_b diag(Dt) Phi_b^T, augmented with identity
    for (int idx = tid; idx < NTAIL*NTAIL; idx += blockDim.x) {
        int i = idx / NTAIL, j = idx % NTAIL;
        double acc = 0.0;
        for (int p = 0; p < NP; p++)
            acc += gd_Phib[i*NP+p] * gd_Dt[p] * gd_Phib[j*NP+p];
        gd_G[i*60 + j] = acc;
        gd_G[i*60 + 30 + j] = (i == j) ? 1.0 : 0.0;
    }
    __syncthreads();
    // Gauss-Jordan (G is SPD: no pivoting)
    __shared__ double fac[NTAIL];
    __shared__ double piv;
    for (int k = 0; k < NTAIL; k++) {
        if (tid == 0) piv = 1.0 / gd_G[k*60 + k];
        __syncthreads();
        for (int j = tid; j < 60; j += blockDim.x) gd_G[k*60 + j] *= piv;
        __syncthreads();
        if (tid < NTAIL && tid != k) fac[tid] = gd_G[tid*60 + k];
        __syncthreads();
        for (int idx = tid; idx < NTAIL*60; idx += blockDim.x) {
            int i = idx / 60, j = idx % 60;
            if (i != k) gd_G[idx] -= fac[i] * gd_G[k*60 + j];
        }
        __syncthreads();
    }
    // PhibTQ[p][n] = Dt[p] * sum_j Phib[j][p] * Q[j][n]
    for (int idx = tid; idx < NP*NTAIL; idx += blockDim.x) {
        int p = idx / NTAIL, n = idx % NTAIL;
        double acc = 0.0;
        for (int j = 0; j < NTAIL; j++)
            acc += gd_Phib[j*NP+p] * gd_G[j*60 + 30 + n];
        double v = gd_Dt[p] * acc;
        gd_PhibTQ[idx] = v;
        g_PhibTQ[idx] = (float)v;
    }
    __syncthreads();
    // M2[k][n] = sum_p C[k][p] * PhibTQ[p][n]
    if (tid < 2*NTAIL) {
        int k = tid / NTAIL, n = tid % NTAIL;
        double acc = 0.0;
        for (int p = 0; p < NP; p++)
            acc += gd_C[k*NP+p] * gd_PhibTQ[p*NTAIL + n];
        g_M2[k*NTAIL+n] = (float)acc;
    }
    for (int idx = tid; idx < NC*NP; idx += blockDim.x)
        g_Phi[idx] = (float)gd_Phi[idx];
    // Phi_out: Chebyshev at t_out
    if (tid < TEV) {
        double tt = -1.0 + 2.0*((double)t_eval[tid] - t0)/dtt;
        double Tm2 = 1.0, Tm1 = tt;
        g_PhiOut[0*TEV+tid] = 1.0f;
        g_PhiOut[1*TEV+tid] = (float)tt;
        #pragma unroll
        for (int n = 2; n < NC; n++) {
            double Tn = 2.0*tt*Tm1 - Tm2;
            g_PhiOut[n*TEV+tid] = (float)Tn; Tm2 = Tm1; Tm1 = Tn;
        }
    }
}

// ---------------- generic copy ---------------------------------------------
__global__ void k_copy(const float* __restrict__ src, float* __restrict__ dst, int n) {
    int i = blockIdx.x * blockDim.x + threadIdx.x;
    int stride = gridDim.x * blockDim.x;
    for (; i < n; i += stride) dst[i] = src[i];
}

__global__ void k_copy_if_done(int par) {
    if (!g_done) return;
    const float* src = g_B[par];
    float* dst = g_B[par ^ 1];
    int i = blockIdx.x * blockDim.x + threadIdx.x;
    int stride = gridDim.x * blockDim.x;
    for (; i < BSZ; i += stride) dst[i] = src[i];
}

__global__ void k_yf2(const float* __restrict__ y_init) {
    int i = blockIdx.x * blockDim.x + threadIdx.x;
    if (i < BATCH*DIM) {
        g_yf2[2*i]   = y_init[i];
        g_yf2[2*i+1] = g_fi[i];
    }
}

// ---------------- SGEMM 128x128x8, 8x8 per thread ---------------------------
// TMODE 0: t = g_tcheb[row & 63]; TMODE 1: t = tvec[0]
template<bool CHECK, int TMODE>
__launch_bounds__(256, 2)
__global__ void sgemm_tanh(const float* __restrict__ A, const float* __restrict__ B,
                           float* __restrict__ C, const float* __restrict__ bias,
                           const float* __restrict__ tvec, int M, int N, int K) {
    if (CHECK && g_done) return;
    __shared__ __align__(16) float As[8][128];
    __shared__ __align__(16) float Bs[8][128];
    const int tid = threadIdx.x;
    const int bm = blockIdx.y * 128, bn = blockIdx.x * 128;
    const int aRow = tid >> 1, aCol = (tid & 1) * 4;
    const int bRow = tid >> 5, bCol = (tid & 31) * 4;
    const int tx = (tid & 15) * 8, ty = (tid >> 4) * 8;
    float acc[8][8];
    #pragma unroll
    for (int i = 0; i < 8; i++)
        #pragma unroll
        for (int j = 0; j < 8; j++) acc[i][j] = 0.0f;

    const float* Ag = A + (long)(bm + aRow) * K + aCol;
    const float* Bg = B + (long)bRow * N + bn + bCol;
    for (int k0 = 0; k0 < K; k0 += 8) {
        float4 av = *(const float4*)(Ag + k0);
        float4 bv = *(const float4*)(Bg + (long)k0 * N);
        As[aCol+0][aRow] = av.x; As[aCol+1][aRow] = av.y;
        As[aCol+2][aRow] = av.z; As[aCol+3][aRow] = av.w;
        *(float4*)&Bs[bRow][bCol] = bv;
        __syncthreads();
        #pragma unroll
        for (int k = 0; k < 8; k++) {
            float4 a0 = *(const float4*)&As[k][ty];
            float4 a1 = *(const float4*)&As[k][ty+4];
            float4 b0 = *(const float4*)&Bs[k][tx];
            float4 b1 = *(const float4*)&Bs[k][tx+4];
            float ar[8] = {a0.x,a0.y,a0.z,a0.w,a1.x,a1.y,a1.z,a1.w};
            float br[8] = {b0.x,b0.y,b0.z,b0.w,b1.x,b1.y,b1.z,b1.w};
            #pragma unroll
            for (int i = 0; i < 8; i++)
                #pragma unroll
                for (int j = 0; j < 8; j++) acc[i][j] += ar[i]*br[j];
        }
        __syncthreads();
    }
    #pragma unroll
    for (int i = 0; i < 8; i++) {
        int row = bm + ty + i;
        float tval = (TMODE == 0) ? g_tcheb[row & 63] : tvec[0];
        #pragma unroll
        for (int j = 0; j < 8; j++) {
            int col = bn + tx + j;
            C[(long)row*N + col] = tanhf(acc[i][j] + bias[col] + tval);
        }
    }
}

template<bool CHECK>
__launch_bounds__(256, 2)
__global__ void sgemm_bias(const float* __restrict__ A, const float* __restrict__ B,
                           float* __restrict__ C, const float* __restrict__ bias,
                           int M, int N, int K) {
    if (CHECK && g_done) return;
    __shared__ __align__(16) float As[8][128];
    __shared__ __align__(16) float Bs[8][128];
    const int tid = threadIdx.x;
    const int bm = blockIdx.y * 128, bn = blockIdx.x * 128;
    const int aRow = tid >> 1, aCol = (tid & 1) * 4;
    const int bRow = tid >> 5, bCol = (tid & 31) * 4;
    const int tx = (tid & 15) * 8, ty = (tid >> 4) * 8;
    float acc[8][8];
    #pragma unroll
    for (int i = 0; i < 8; i++)
        #pragma unroll
        for (int j = 0; j < 8; j++) acc[i][j] = 0.0f;

    const float* Ag = A + (long)(bm + aRow) * K + aCol;
    const float* Bg = B + (long)bRow * N + bn + bCol;
    for (int k0 = 0; k0 < K; k0 += 8) {
        float4 av = *(const float4*)(Ag + k0);
        float4 bv = *(const float4*)(Bg + (long)k0 * N);
        As[aCol+0][aRow] = av.x; As[aCol+1][aRow] = av.y;
        As[aCol+2][aRow] = av.z; As[aCol+3][aRow] = av.w;
        *(float4*)&Bs[bRow][bCol] = bv;
        __syncthreads();
        #pragma unroll
        for (int k = 0; k < 8; k++) {
            float4 a0 = *(const float4*)&As[k][ty];
            float4 a1 = *(const float4*)&As[k][ty+4];
            float4 b0 = *(const float4*)&Bs[k][tx];
            float4 b1 = *(const float4*)&Bs[k][tx+4];
            float ar[8] = {a0.x,a0.y,a0.z,a0.w,a1.x,a1.y,a1.z,a1.w};
            float br[8] = {b0.x,b0.y,b0.z,b0.w,b1.x,b1.y,b1.z,b1.w};
            #pragma unroll
            for (int i = 0; i < 8; i++)
                #pragma unroll
                for (int j = 0; j < 8; j++) acc[i][j] += ar[i]*br[j];
        }
        __syncthreads();
    }
    #pragma unroll
    for (int i = 0; i < 8; i++) {
        int row = bm + ty + i;
        #pragma unroll
        for (int j = 0; j < 8; j++) {
            int col = bn + tx + j;
            C[(long)row*N + col] = acc[i][j] + bias[col];
        }
    }
}

// ---------------- build B_full and y_grid -----------------------------------
// y_grid[b,p,d] = sum_n B_full[b,d,n] * Phi[n,p]
__global__ void k_ygrid(int par) {
    if (g_done) return;
    __shared__ float sPhi[NC][NP];
    int tid = threadIdx.x, b = blockIdx.x;
    for (int i = tid; i < NC*NP; i += blockDim.x)
        ((float*)sPhi)[i] = g_Phi[i];
    __syncthreads();
    int d = tid;
    const float* Brow = g_B[par] + (long)(b*DIM + d) * NTAIL;
    float r0 = g_yf2[(b*DIM + d)*2 + 0];
    float r1 = g_yf2[(b*DIM + d)*2 + 1];
    float c[NC];
    #pragma unroll
    for (int j = 0; j < NTAIL; j++) {
        float bj = Brow[j];
        c[j+2] = bj;
        r0 -= bj * g_PD2[j*2+0];
        r1 -= bj * g_PD2[j*2+1];
    }
    c[0] = r0 * g_inv0[0] + r1 * g_inv0[2];
    c[1] = r0 * g_inv0[1] + r1 * g_inv0[3];
    for (int p = 0; p < NP; p++) {
        float acc = 0.0f;
        #pragma unroll
        for (int n = 0; n < NC; n++) acc += c[n] * sPhi[n][p];
        g_yg[((long)b*NP + p)*DIM + d] = acc;
    }
}

// ---------------- B_new + delta partial sums --------------------------------
__global__ void k_bnew(int par, int iter) {
    if (g_done) return;
    __shared__ float sP[NP][NTAIL];
    __shared__ float sM2[2][NTAIL];
    int tid = threadIdx.x, b = blockIdx.x;
    for (int i = tid; i < NP*NTAIL; i += blockDim.x) ((float*)sP)[i] = g_PhibTQ[i];
    if (tid < 2*NTAIL) ((float*)sM2)[tid] = g_M2[tid];
    __syncthreads();
    int d = tid;
    float acc[NTAIL];
    #pragma unroll
    for (int n = 0; n < NTAIL; n++) acc[n] = 0.0f;
    for (int p = 0; p < NP; p++) {
        float v = g_f[((long)b*NP + p)*DIM + d];
        #pragma unroll
        for (int n = 0; n < NTAIL; n++) acc[n] += v * sP[p][n];
    }
    float y0 = g_yf2[(b*DIM + d)*2 + 0];
    float y1 = g_yf2[(b*DIM + d)*2 + 1];
    const float* Bp = g_B[par] + (long)(b*DIM + d) * NTAIL;
    float* Bn = g_B[par ^ 1] + (long)(b*DIM + d) * NTAIL;
    float ss = 0.0f;
    #pragma unroll
    for (int n = 0; n < NTAIL; n++) {
        float val = acc[n] - y0 * sM2[0][n] - y1 * sM2[1][n];
        Bn[n] = val;
        float df = val - Bp[n];
        ss += df * df;
    }
    // deterministic block reduction
    #pragma unroll
    for (int o = 16; o > 0; o >>= 1) ss += __shfl_down_sync(0xffffffffu, ss, o);
    __shared__ float wsum[8];
    if ((tid & 31) == 0) wsum[tid >> 5] = ss;
    __syncthreads();
    if (tid == 0) {
        float t = 0.0f;
        #pragma unroll
        for (int w = 0; w < 8; w++) t += wsum[w];
        g_bsum[b] = t;
    }
}

__global__ void k_finalize(int iter) {
    int tid = threadIdx.x;  // 256 threads
    __shared__ float sh[256];
    if (g_done) return;
    float s = g_bsum[tid] + g_bsum[tid + 256];
    sh[tid] = s;
    __syncthreads();
    for (int o = 128; o > 0; o >>= 1) {
        if (tid < o) sh[tid] += sh[tid + o];
        __syncthreads();
    }
    if (tid == 0) {
        float d = sqrtf(sh[0]);
        g_delta = d;
        if (d < TOLF) g_done = 1;
    }
}

// ---------------- final trajectory ------------------------------------------
__global__ void k_traj(float* __restrict__ out_traj) {
    __shared__ float sPO[NC*TEV];
    int tid = threadIdx.x, b = blockIdx.x;
    for (int i = tid; i < NC*TEV; i += blockDim.x) sPO[i] = g_PhiOut[i];
    __syncthreads();
    int d = tid;
    const float* Brow = g_B[0] + (long)(b*DIM + d) * NTAIL;
    float r0 = g_yf2[(b*DIM + d)*2 + 0];
    float r1 = g_yf2[(b*DIM + d)*2 + 1];
    float c[NC];
    #pragma unroll
    for (int j = 0; j < NTAIL; j++) {
        float bj = Brow[j];
        c[j+2] = bj;
        r0 -= bj * g_PD2[j*2+0];
        r1 -= bj * g_PD2[j*2+1];
    }
    c[0] = r0 * g_inv0[0] + r1 * g_inv0[2];
    c[1] = r0 * g_inv0[1] + r1 * g_inv0[3];
    #pragma unroll
    for (int t = 0; t < TEV; t++) {
        float acc = 0.0f;
        #pragma unroll
        for (int n = 0; n < NC; n++) acc += c[n] * sPO[n*TEV + t];
        out_traj[((long)t*BATCH + b)*DIM + d] = acc;
    }
}

__global__ void k_misc(const float* __restrict__ t_eval, float* __restrict__ out, int tn) {
    int tid = threadIdx.x;
    if (tid < tn) out[tid] = t_eval[tid];
    if (tid == 31) out[DELTA_OFF] = g_delta;
}

// ---------------- launch ----------------------------------------------------
extern "C" void kernel_launch(void* const* d_in, const int* in_sizes, int n_in,
                              void* d_out, int out_size) {
    const float* y_init = (const float*)d_in[0];
    const float* t_eval = (const float*)d_in[1];
    const float* B_init = (const float*)d_in[2];
    const float* W1 = (const float*)d_in[3];
    const float* b1 = (const float*)d_in[4];
    const float* W2 = (const float*)d_in[5];
    const float* b2 = (const float*)d_in[6];
    float* out = (float*)d_out;
    int tn = in_sizes[1];

    float *pB0, *pyg, *ph, *pf, *ph0, *pfi;
    cudaGetSymbolAddress((void**)&pB0, g_B);
    cudaGetSymbolAddress((void**)&pyg, g_yg);
    cudaGetSymbolAddress((void**)&ph,  g_h);
    cudaGetSymbolAddress((void**)&pf,  g_f);
    cudaGetSymbolAddress((void**)&ph0, g_h0);
    cudaGetSymbolAddress((void**)&pfi, g_fi);

    k_precompute<<<1, 256>>>(t_eval, tn);
    k_copy<<<2048, 256>>>(B_init, pB0, BSZ);

    // f_init = vf_point(t0, y_init)
    sgemm_tanh<false, 1><<<dim3(HID/128, BATCH/128), 256>>>(
        y_init, W1, ph0, b1, t_eval, BATCH, HID, DIM);
    sgemm_bias<false><<<dim3(DIM/128, BATCH/128), 256>>>(
        ph0, W2, pfi, b2, BATCH, DIM, HID);
    k_yf2<<<(BATCH*DIM + 255)/256, 256>>>(y_init);

    for (int it = 0; it < MAXIT; it++) {
        int par = it & 1;
        k_ygrid<<<BATCH, 256>>>(par);
        sgemm_tanh<true, 0><<<dim3(HID/128, MROWS/128), 256>>>(
            pyg, W1, ph, b1, t_eval, MROWS, HID, DIM);
        sgemm_bias<true><<<dim3(DIM/128, MROWS/128), 256>>>(
            ph, W2, pf, b2, MROWS, DIM, HID);
        k_bnew<<<BATCH, 256>>>(par, it);
        k_copy_if_done<<<2048, 256>>>(par);
        k_finalize<<<1, 256>>>(it);
    }

    // final B lives in g_B[0] after 10 iterations
    k_traj<<<BATCH, 256>>>(out + TEV);
    k_misc<<<1, 32>>>(t_eval, out, tn);
    k_copy<<<2048, 256>>>(pB0, out + B_OFF, BSZ);
}

// round 6
// speedup vs baseline: 1.1235x; 1.1235x over previous
#include <cuda_runtime.h>
#include <math_constants.h>

#define BATCH 512
#define DIM   256
#define HID   512
#define NC    32      // NUM_COEFF
#define NTAIL 30      // NUM_COEFF - 2
#define NP    64      // Chebyshev points
#define TEV   16
#define MAXIT 10
#define TOLF  0.01f

#define MROWS (BATCH*NP)          // 32768
#define BSZ   (BATCH*DIM*NTAIL)   // 3,932,160
#define TRAJ_N (TEV*BATCH*DIM)    // 2,097,152
#define DELTA_OFF (TEV + TRAJ_N)  // 2,097,168
#define B_OFF (DELTA_OFF + 1)     // 2,097,169

// ---------------- scratch (device globals; no allocation allowed) ----------
__device__ float g_B[2][BSZ];                 // Picard coefficient ping-pong
__device__ float g_yg[BATCH*NP*DIM];          // y_grid  [b,p,d]
__device__ float g_h [BATCH*NP*HID];          // hidden  [b,p,h]
__device__ float g_f [BATCH*NP*DIM];          // fapprox [b,p,d]
__device__ float g_yf2[BATCH*DIM*2];
__device__ float g_h0[BATCH*HID];
__device__ float g_fi[BATCH*DIM];
__device__ float g_bsum[BATCH];

// small fp32 operators
__device__ float g_Phi[NC*NP];
__device__ float g_tcheb[NP];
__device__ float g_PD2[NTAIL*2];
__device__ float g_inv0[4];
__device__ float g_PhibTQ[NP*NTAIL];
__device__ float g_M2[2*NTAIL];
__device__ float g_PhiOut[NC*TEV];
__device__ float g_delta;
__device__ int   g_done;

// double precompute workspace
__device__ double gd_tcheb[NP];
__device__ double gd_Dt[NP];
__device__ double gd_Phi[NC*NP];
__device__ double gd_DPhi[NC*NP];
__device__ double gd_C[2*NP];
__device__ double gd_Phib[NTAIL*NP];
__device__ double gd_G[NTAIL*60];       // augmented [G | I]
__device__ double gd_PhibTQ[NP*NTAIL];

#define DPI 3.14159265358979323846

// ---------------- precompute spectral operators (1 block) ------------------
__global__ void k_precompute(const float* __restrict__ t_eval, int tn) {
    int tid = threadIdx.x;
    double t0 = (double)t_eval[0];
    double t1 = (double)t_eval[tn-1];
    double dtt = t1 - t0;
    double sg = (dtt > 0.0) ? 1.0 : ((dtt < 0.0) ? -1.0 : 0.0);
    double s = 2.0 / dtt;

    if (tid < NP) {
        double tc = -sg * cos(DPI * (double)tid / (double)NP);
        gd_tcheb[tid] = tc;
        g_tcheb[tid] = (float)tc;
        double Tm2 = 1.0, Tm1 = tc;
        gd_Phi[0*NP+tid] = 1.0;
        gd_Phi[1*NP+tid] = tc;
        #pragma unroll
        for (int n = 2; n < NC; n++) {
            double Tn = 2.0*tc*Tm1 - Tm2;
            gd_Phi[n*NP+tid] = Tn; Tm2 = Tm1; Tm1 = Tn;
        }
        double Um1 = 1.0, U = 2.0*tc;
        gd_DPhi[0*NP+tid] = 0.0;
        gd_DPhi[1*NP+tid] = s * 1.0 * Um1;
        gd_DPhi[2*NP+tid] = s * 2.0 * U;
        #pragma unroll
        for (int k = 3; k < NC; k++) {
            double Un = 2.0*tc*U - Um1;
            Um1 = U; U = Un;
            gd_DPhi[k*NP+tid] = s * (double)k * U;
        }
    }
    __syncthreads();
    if (tid < NP)
        gd_Dt[tid] = (tid < NP-1) ? (gd_tcheb[tid+1] - gd_tcheb[tid])
                                  : (1.0 - gd_tcheb[NP-1]);

    __shared__ double sinv0[4];
    if (tid == 0) {
        double a = gd_Phi[0], b = gd_DPhi[0];
        double c = gd_Phi[1*NP], d = gd_DPhi[1*NP];
        double det = a*d - b*c;
        sinv0[0] =  d/det; sinv0[1] = -b/det;
        sinv0[2] = -c/det; sinv0[3] =  a/det;
        g_inv0[0]=(float)sinv0[0]; g_inv0[1]=(float)sinv0[1];
        g_inv0[2]=(float)sinv0[2]; g_inv0[3]=(float)sinv0[3];
        g_done = 0;
        g_delta = CUDART_INF_F;
    }
    __syncthreads();
    if (tid < 2*NP) {
        int k = tid / NP, p = tid % NP;
        gd_C[k*NP+p] = sinv0[k*2+0]*gd_DPhi[0*NP+p] + sinv0[k*2+1]*gd_DPhi[1*NP+p];
    }
    if (tid < NTAIL) {
        g_PD2[tid*2+0] = (float)gd_Phi [(tid+2)*NP + 0];
        g_PD2[tid*2+1] = (float)gd_DPhi[(tid+2)*NP + 0];
    }
    __syncthreads();
    for (int idx = tid; idx < NTAIL*NP; idx += blockDim.x) {
        int j = idx / NP, p = idx % NP;
        double pd0 = gd_Phi [(j+2)*NP + 0];
        double pd1 = gd_DPhi[(j+2)*NP + 0];
        gd_Phib[idx] = gd_DPhi[(j+2)*NP + p] - pd0*gd_C[0*NP+p] - pd1*gd_C[1*NP+p];
    }
    __syncthreads();
    for (int idx = tid; idx < NTAIL*NTAIL; idx += blockDim.x) {
        int i = idx / NTAIL, j = idx % NTAIL;
        double acc = 0.0;
        for (int p = 0; p < NP; p++)
            acc += gd_Phib[i*NP+p] * gd_Dt[p] * gd_Phib[j*NP+p];
        gd_G[i*60 + j] = acc;
        gd_G[i*60 + 30 + j] = (i == j) ? 1.0 : 0.0;
    }
    __syncthreads();
    __shared__ double fac[NTAIL];
    __shared__ double piv;
    for (int k = 0; k < NTAIL; k++) {
        if (tid == 0) piv = 1.0 / gd_G[k*60 + k];
        __syncthreads();
        for (int j = tid; j < 60; j += blockDim.x) gd_G[k*60 + j] *= piv;
        __syncthreads();
        if (tid < NTAIL && tid != k) fac[tid] = gd_G[tid*60 + k];
        __syncthreads();
        for (int idx = tid; idx < NTAIL*60; idx += blockDim.x) {
            int i = idx / 60, j = idx % 60;
            if (i != k) gd_G[idx] -= fac[i] * gd_G[k*60 + j];
        }
        __syncthreads();
    }
    for (int idx = tid; idx < NP*NTAIL; idx += blockDim.x) {
        int p = idx / NTAIL, n = idx % NTAIL;
        double acc = 0.0;
        for (int j = 0; j < NTAIL; j++)
            acc += gd_Phib[j*NP+p] * gd_G[j*60 + 30 + n];
        double v = gd_Dt[p] * acc;
        gd_PhibTQ[idx] = v;
        g_PhibTQ[idx] = (float)v;
    }
    __syncthreads();
    if (tid < 2*NTAIL) {
        int k = tid / NTAIL, n = tid % NTAIL;
        double acc = 0.0;
        for (int p = 0; p < NP; p++)
            acc += gd_C[k*NP+p] * gd_PhibTQ[p*NTAIL + n];
        g_M2[k*NTAIL+n] = (float)acc;
    }
    for (int idx = tid; idx < NC*NP; idx += blockDim.x)
        g_Phi[idx] = (float)gd_Phi[idx];
    if (tid < TEV) {
        double tt = -1.0 + 2.0*((double)t_eval[tid] - t0)/dtt;
        double Tm2 = 1.0, Tm1 = tt;
        g_PhiOut[0*TEV+tid] = 1.0f;
        g_PhiOut[1*TEV+tid] = (float)tt;
        #pragma unroll
        for (int n = 2; n < NC; n++) {
            double Tn = 2.0*tt*Tm1 - Tm2;
            g_PhiOut[n*TEV+tid] = (float)Tn; Tm2 = Tm1; Tm1 = Tn;
        }
    }
}

// ---------------- generic copy ---------------------------------------------
__global__ void k_copy(const float* __restrict__ src, float* __restrict__ dst, int n) {
    int i = blockIdx.x * blockDim.x + threadIdx.x;
    int stride = gridDim.x * blockDim.x;
    for (; i < n; i += stride) dst[i] = src[i];
}

__global__ void k_copy_if_done(int par) {
    if (!g_done) return;
    const float* src = g_B[par];
    float* dst = g_B[par ^ 1];
    int i = blockIdx.x * blockDim.x + threadIdx.x;
    int stride = gridDim.x * blockDim.x;
    for (; i < BSZ; i += stride) dst[i] = src[i];
}

__global__ void k_yf2(const float* __restrict__ y_init) {
    int i = blockIdx.x * blockDim.x + threadIdx.x;
    if (i < BATCH*DIM) {
        g_yf2[2*i]   = y_init[i];
        g_yf2[2*i+1] = g_fi[i];
    }
}

// ---------------- SGEMM 128x128, K-chunk 16, reg-double-buffered ------------
// Bit-identical accumulation to the R2 kernel: per output element, a single
// FFMA chain over ascending k. Only the schedule differs.
// EPI 0: C = tanhf(acc + bias + t)   EPI 1: C = acc + bias
// TMODE 0: t = g_tcheb[row & 63]; TMODE 1: t = tvec[0]
template<int EPI, int TMODE, bool CHECK>
__launch_bounds__(256, 2)
__global__ void sgemm(const float* __restrict__ A, const float* __restrict__ B,
                      float* __restrict__ C, const float* __restrict__ bias,
                      const float* __restrict__ tvec, int M, int N, int K) {
    if (CHECK && g_done) return;
    __shared__ __align__(16) float As[2][16][132];   // [k][row], padded
    __shared__ __align__(16) float Bs[2][16][128];   // [k][col]
    const int tid = threadIdx.x;
    const int bm = blockIdx.y * 128, bn = blockIdx.x * 128;
    const int tx = (tid & 15) * 8, ty = (tid >> 4) * 8;
    const int NCH = K >> 4;

    float acc[8][8];
    #pragma unroll
    for (int i = 0; i < 8; i++)
        #pragma unroll
        for (int j = 0; j < 8; j++) acc[i][j] = 0.0f;

    float4 ra[2], rb[2];
    auto gload = [&](int c) {
        int k0 = c << 4;
        #pragma unroll
        for (int i = 0; i < 2; i++) {
            int idx = (i << 8) + tid;
            ra[i] = *(const float4*)(A + (long)(bm + (idx >> 2)) * K + k0 + ((idx & 3) << 2));
            rb[i] = *(const float4*)(B + (long)(k0 + (idx >> 5)) * N + bn + ((idx & 31) << 2));
        }
    };
    auto sstore = [&](int s) {
        #pragma unroll
        for (int i = 0; i < 2; i++) {
            int idx = (i << 8) + tid;
            int row = idx >> 2, c4 = (idx & 3) << 2;
            As[s][c4+0][row] = ra[i].x;
            As[s][c4+1][row] = ra[i].y;
            As[s][c4+2][row] = ra[i].z;
            As[s][c4+3][row] = ra[i].w;
            *(float4*)&Bs[s][idx >> 5][(idx & 31) << 2] = rb[i];
        }
    };

    gload(0);
    sstore(0);
    if (NCH > 1) gload(1);
    __syncthreads();

    for (int c = 0; c < NCH; c++) {
        int s = c & 1;
        if (c + 1 < NCH) sstore(s ^ 1);       // chunk c+1 (regs from prev iter)
        if (c + 2 < NCH) gload(c + 2);        // start next global loads early
        #pragma unroll
        for (int k = 0; k < 16; k++) {
            float4 a0 = *(const float4*)&As[s][k][ty];
            float4 a1 = *(const float4*)&As[s][k][ty+4];
            float4 b0 = *(const float4*)&Bs[s][k][tx];
            float4 b1 = *(const float4*)&Bs[s][k][tx+4];
            float ar[8] = {a0.x,a0.y,a0.z,a0.w,a1.x,a1.y,a1.z,a1.w};
            float br[8] = {b0.x,b0.y,b0.z,b0.w,b1.x,b1.y,b1.z,b1.w};
            #pragma unroll
            for (int i = 0; i < 8; i++)
                #pragma unroll
                for (int j = 0; j < 8; j++) acc[i][j] += ar[i]*br[j];
        }
        __syncthreads();
    }

    // epilogue (same arithmetic expressions as the passing R2 kernel)
    float bv[8];
    *(float4*)&bv[0] = *(const float4*)&bias[bn + tx];
    *(float4*)&bv[4] = *(const float4*)&bias[bn + tx + 4];
    float tv1 = 0.0f;
    if (EPI == 0 && TMODE == 1) tv1 = tvec[0];
    #pragma unroll
    for (int i = 0; i < 8; i++) {
        int row = bm + ty + i;
        float v[8];
        if (EPI == 0) {
            float tval = (TMODE == 0) ? g_tcheb[row & 63] : tv1;
            #pragma unroll
            for (int j = 0; j < 8; j++) v[j] = tanhf(acc[i][j] + bv[j] + tval);
        } else {
            #pragma unroll
            for (int j = 0; j < 8; j++) v[j] = acc[i][j] + bv[j];
        }
        *(float4*)&C[(long)row*N + bn + tx]     = *(float4*)&v[0];
        *(float4*)&C[(long)row*N + bn + tx + 4] = *(float4*)&v[4];
    }
}

// ---------------- build B_full and y_grid -----------------------------------
__global__ void k_ygrid(int par) {
    if (g_done) return;
    __shared__ float sPhi[NC][NP];
    int tid = threadIdx.x, b = blockIdx.x;
    for (int i = tid; i < NC*NP; i += blockDim.x)
        ((float*)sPhi)[i] = g_Phi[i];
    __syncthreads();
    int d = tid;
    const float* Brow = g_B[par] + (long)(b*DIM + d) * NTAIL;
    float r0 = g_yf2[(b*DIM + d)*2 + 0];
    float r1 = g_yf2[(b*DIM + d)*2 + 1];
    float c[NC];
    #pragma unroll
    for (int j = 0; j < NTAIL; j++) {
        float bj = Brow[j];
        c[j+2] = bj;
        r0 -= bj * g_PD2[j*2+0];
        r1 -= bj * g_PD2[j*2+1];
    }
    c[0] = r0 * g_inv0[0] + r1 * g_inv0[2];
    c[1] = r0 * g_inv0[1] + r1 * g_inv0[3];
    for (int p = 0; p < NP; p++) {
        float acc = 0.0f;
        #pragma unroll
        for (int n = 0; n < NC; n++) acc += c[n] * sPhi[n][p];
        g_yg[((long)b*NP + p)*DIM + d] = acc;
    }
}

// ---------------- B_new + delta partial sums --------------------------------
__global__ void k_bnew(int par) {
    if (g_done) return;
    __shared__ float sP[NP][NTAIL];
    __shared__ float sM2[2][NTAIL];
    int tid = threadIdx.x, b = blockIdx.x;
    for (int i = tid; i < NP*NTAIL; i += blockDim.x) ((float*)sP)[i] = g_PhibTQ[i];
    if (tid < 2*NTAIL) ((float*)sM2)[tid] = g_M2[tid];
    __syncthreads();
    int d = tid;
    float acc[NTAIL];
    #pragma unroll
    for (int n = 0; n < NTAIL; n++) acc[n] = 0.0f;
    for (int p = 0; p < NP; p++) {
        float v = g_f[((long)b*NP + p)*DIM + d];
        #pragma unroll
        for (int n = 0; n < NTAIL; n++) acc[n] += v * sP[p][n];
    }
    float y0 = g_yf2[(b*DIM + d)*2 + 0];
    float y1 = g_yf2[(b*DIM + d)*2 + 1];
    const float* Bp = g_B[par] + (long)(b*DIM + d) * NTAIL;
    float* Bn = g_B[par ^ 1] + (long)(b*DIM + d) * NTAIL;
    float ss = 0.0f;
    #pragma unroll
    for (int n = 0; n < NTAIL; n++) {
        float val = acc[n] - y0 * sM2[0][n] - y1 * sM2[1][n];
        Bn[n] = val;
        float df = val - Bp[n];
        ss += df * df;
    }
    #pragma unroll
    for (int o = 16; o > 0; o >>= 1) ss += __shfl_down_sync(0xffffffffu, ss, o);
    __shared__ float wsum[8];
    if ((tid & 31) == 0) wsum[tid >> 5] = ss;
    __syncthreads();
    if (tid == 0) {
        float t = 0.0f;
        #pragma unroll
        for (int w = 0; w < 8; w++) t += wsum[w];
        g_bsum[b] = t;
    }
}

__global__ void k_finalize() {
    int tid = threadIdx.x;  // 256 threads
    __shared__ float sh[256];
    if (g_done) return;
    float s = g_bsum[tid] + g_bsum[tid + 256];
    sh[tid] = s;
    __syncthreads();
    for (int o = 128; o > 0; o >>= 1) {
        if (tid < o) sh[tid] += sh[tid + o];
        __syncthreads();
    }
    if (tid == 0) {
        float d = sqrtf(sh[0]);
        g_delta = d;
        if (d < TOLF) g_done = 1;
    }
}

// ---------------- final trajectory ------------------------------------------
__global__ void k_traj(float* __restrict__ out_traj) {
    __shared__ float sPO[NC*TEV];
    int tid = threadIdx.x, b = blockIdx.x;
    for (int i = tid; i < NC*TEV; i += blockDim.x) sPO[i] = g_PhiOut[i];
    __syncthreads();
    int d = tid;
    const float* Brow = g_B[0] + (long)(b*DIM + d) * NTAIL;
    float r0 = g_yf2[(b*DIM + d)*2 + 0];
    float r1 = g_yf2[(b*DIM + d)*2 + 1];
    float c[NC];
    #pragma unroll
    for (int j = 0; j < NTAIL; j++) {
        float bj = Brow[j];
        c[j+2] = bj;
        r0 -= bj * g_PD2[j*2+0];
        r1 -= bj * g_PD2[j*2+1];
    }
    c[0] = r0 * g_inv0[0] + r1 * g_inv0[2];
    c[1] = r0 * g_inv0[1] + r1 * g_inv0[3];
    #pragma unroll
    for (int t = 0; t < TEV; t++) {
        float acc = 0.0f;
        #pragma unroll
        for (int n = 0; n < NC; n++) acc += c[n] * sPO[n*TEV + t];
        out_traj[((long)t*BATCH + b)*DIM + d] = acc;
    }
}

__global__ void k_misc(const float* __restrict__ t_eval, float* __restrict__ out, int tn) {
    int tid = threadIdx.x;
    if (tid < tn) out[tid] = t_eval[tid];
    if (tid == 31) out[DELTA_OFF] = g_delta;
}

// ---------------- launch ----------------------------------------------------
extern "C" void kernel_launch(void* const* d_in, const int* in_sizes, int n_in,
                              void* d_out, int out_size) {
    const float* y_init = (const float*)d_in[0];
    const float* t_eval = (const float*)d_in[1];
    const float* B_init = (const float*)d_in[2];
    const float* W1 = (const float*)d_in[3];
    const float* b1 = (const float*)d_in[4];
    const float* W2 = (const float*)d_in[5];
    const float* b2 = (const float*)d_in[6];
    float* out = (float*)d_out;
    int tn = in_sizes[1];

    float *pB0, *pyg, *ph, *pf, *ph0, *pfi;
    cudaGetSymbolAddress((void**)&pB0, g_B);
    cudaGetSymbolAddress((void**)&pyg, g_yg);
    cudaGetSymbolAddress((void**)&ph,  g_h);
    cudaGetSymbolAddress((void**)&pf,  g_f);
    cudaGetSymbolAddress((void**)&ph0, g_h0);
    cudaGetSymbolAddress((void**)&pfi, g_fi);

    k_precompute<<<1, 256>>>(t_eval, tn);
    k_copy<<<2048, 256>>>(B_init, pB0, BSZ);

    // f_init = vf_point(t0, y_init)
    sgemm<0, 1, false><<<dim3(HID/128, BATCH/128), 256>>>(
        y_init, W1, ph0, b1, t_eval, BATCH, HID, DIM);
    sgemm<1, 0, false><<<dim3(DIM/128, BATCH/128), 256>>>(
        ph0, W2, pfi, b2, t_eval, BATCH, DIM, HID);
    k_yf2<<<(BATCH*DIM + 255)/256, 256>>>(y_init);

    for (int it = 0; it < MAXIT; it++) {
        int par = it & 1;
        k_ygrid<<<BATCH, 256>>>(par);
        sgemm<0, 0, true><<<dim3(HID/128, MROWS/128), 256>>>(
            pyg, W1, ph, b1, t_eval, MROWS, HID, DIM);
        sgemm<1, 0, true><<<dim3(DIM/128, MROWS/128), 256>>>(
            ph, W2, pf, b2, t_eval, MROWS, DIM, HID);
        k_bnew<<<BATCH, 256>>>(par);
        k_copy_if_done<<<2048, 256>>>(par);
        k_finalize<<<1, 256>>>();
    }

    // final B lives in g_B[0] after 10 iterations
    k_traj<<<BATCH, 256>>>(out + TEV);
    k_misc<<<1, 32>>>(t_eval, out, tn);
    k_copy<<<2048, 256>>>(pB0, out + B_OFF, BSZ);
}

// round 7
// speedup vs baseline: 1.2069x; 1.0742x over previous
#include <cuda_runtime.h>
#include <math_constants.h>

#define BATCH 512
#define DIM   256
#define HID   512
#define NC    32      // NUM_COEFF
#define NTAIL 30      // NUM_COEFF - 2
#define NP    64      // Chebyshev points
#define TEV   16
#define MAXIT 10
#define TOLF  0.01f

#define MROWS (BATCH*NP)          // 32768
#define BSZ   (BATCH*DIM*NTAIL)   // 3,932,160
#define TRAJ_N (TEV*BATCH*DIM)    // 2,097,152
#define DELTA_OFF (TEV + TRAJ_N)  // 2,097,168
#define B_OFF (DELTA_OFF + 1)     // 2,097,169

// ---------------- scratch (device globals; no allocation allowed) ----------
__device__ float g_B[2][BSZ];                 // Picard coefficient ping-pong
__device__ float g_yg[BATCH*NP*DIM];          // y_grid  [b,p,d]
__device__ float g_h [BATCH*NP*HID];          // hidden  [b,p,h]
__device__ float g_f [BATCH*NP*DIM];          // fapprox [b,p,d]
__device__ float g_yf2[BATCH*DIM*2];
__device__ float g_h0[BATCH*HID];
__device__ float g_fi[BATCH*DIM];
__device__ float g_bsum[BATCH];

// small fp32 operators
__device__ float g_Phi[NC*NP];
__device__ float g_tcheb[NP];
__device__ float g_PD2[NTAIL*2];
__device__ float g_inv0[4];
__device__ float g_PhibTQ[NP*NTAIL];
__device__ float g_M2[2*NTAIL];
__device__ float g_PhiOut[NC*TEV];
__device__ float g_delta;
__device__ int   g_done;

// double precompute workspace
__device__ double gd_tcheb[NP];
__device__ double gd_Dt[NP];
__device__ double gd_Phi[NC*NP];
__device__ double gd_DPhi[NC*NP];
__device__ double gd_C[2*NP];
__device__ double gd_Phib[NTAIL*NP];
__device__ double gd_G[NTAIL*60];       // augmented [G | I]
__device__ double gd_PhibTQ[NP*NTAIL];

#define DPI 3.14159265358979323846

// ---------------- f32x2 helpers (per-lane IEEE fma.rn — bit-identical) -----
__device__ __forceinline__ unsigned long long pk2(float lo, float hi) {
    unsigned long long r;
    asm("mov.b64 %0, {%1, %2};" : "=l"(r) : "f"(lo), "f"(hi));
    return r;
}
__device__ __forceinline__ void upk2(unsigned long long v, float& lo, float& hi) {
    asm("mov.b64 {%0, %1}, %2;" : "=f"(lo), "=f"(hi) : "l"(v));
}
__device__ __forceinline__ unsigned long long fma2(unsigned long long a,
                                                   unsigned long long b,
                                                   unsigned long long c) {
    unsigned long long d;
    asm("fma.rn.f32x2 %0, %1, %2, %3;" : "=l"(d) : "l"(a), "l"(b), "l"(c));
    return d;
}

// ---------------- precompute spectral operators (1 block) ------------------
__global__ void k_precompute(const float* __restrict__ t_eval, int tn) {
    int tid = threadIdx.x;
    double t0 = (double)t_eval[0];
    double t1 = (double)t_eval[tn-1];
    double dtt = t1 - t0;
    double sg = (dtt > 0.0) ? 1.0 : ((dtt < 0.0) ? -1.0 : 0.0);
    double s = 2.0 / dtt;

    if (tid < NP) {
        double tc = -sg * cos(DPI * (double)tid / (double)NP);
        gd_tcheb[tid] = tc;
        g_tcheb[tid] = (float)tc;
        double Tm2 = 1.0, Tm1 = tc;
        gd_Phi[0*NP+tid] = 1.0;
        gd_Phi[1*NP+tid] = tc;
        #pragma unroll
        for (int n = 2; n < NC; n++) {
            double Tn = 2.0*tc*Tm1 - Tm2;
            gd_Phi[n*NP+tid] = Tn; Tm2 = Tm1; Tm1 = Tn;
        }
        double Um1 = 1.0, U = 2.0*tc;
        gd_DPhi[0*NP+tid] = 0.0;
        gd_DPhi[1*NP+tid] = s * 1.0 * Um1;
        gd_DPhi[2*NP+tid] = s * 2.0 * U;
        #pragma unroll
        for (int k = 3; k < NC; k++) {
            double Un = 2.0*tc*U - Um1;
            Um1 = U; U = Un;
            gd_DPhi[k*NP+tid] = s * (double)k * U;
        }
    }
    __syncthreads();
    if (tid < NP)
        gd_Dt[tid] = (tid < NP-1) ? (gd_tcheb[tid+1] - gd_tcheb[tid])
                                  : (1.0 - gd_tcheb[NP-1]);

    __shared__ double sinv0[4];
    if (tid == 0) {
        double a = gd_Phi[0], b = gd_DPhi[0];
        double c = gd_Phi[1*NP], d = gd_DPhi[1*NP];
        double det = a*d - b*c;
        sinv0[0] =  d/det; sinv0[1] = -b/det;
        sinv0[2] = -c/det; sinv0[3] =  a/det;
        g_inv0[0]=(float)sinv0[0]; g_inv0[1]=(float)sinv0[1];
        g_inv0[2]=(float)sinv0[2]; g_inv0[3]=(float)sinv0[3];
        g_done = 0;
        g_delta = CUDART_INF_F;
    }
    __syncthreads();
    if (tid < 2*NP) {
        int k = tid / NP, p = tid % NP;
        gd_C[k*NP+p] = sinv0[k*2+0]*gd_DPhi[0*NP+p] + sinv0[k*2+1]*gd_DPhi[1*NP+p];
    }
    if (tid < NTAIL) {
        g_PD2[tid*2+0] = (float)gd_Phi [(tid+2)*NP + 0];
        g_PD2[tid*2+1] = (float)gd_DPhi[(tid+2)*NP + 0];
    }
    __syncthreads();
    for (int idx = tid; idx < NTAIL*NP; idx += blockDim.x) {
        int j = idx / NP, p = idx % NP;
        double pd0 = gd_Phi [(j+2)*NP + 0];
        double pd1 = gd_DPhi[(j+2)*NP + 0];
        gd_Phib[idx] = gd_DPhi[(j+2)*NP + p] - pd0*gd_C[0*NP+p] - pd1*gd_C[1*NP+p];
    }
    __syncthreads();
    for (int idx = tid; idx < NTAIL*NTAIL; idx += blockDim.x) {
        int i = idx / NTAIL, j = idx % NTAIL;
        double acc = 0.0;
        for (int p = 0; p < NP; p++)
            acc += gd_Phib[i*NP+p] * gd_Dt[p] * gd_Phib[j*NP+p];
        gd_G[i*60 + j] = acc;
        gd_G[i*60 + 30 + j] = (i == j) ? 1.0 : 0.0;
    }
    __syncthreads();
    __shared__ double fac[NTAIL];
    __shared__ double piv;
    for (int k = 0; k < NTAIL; k++) {
        if (tid == 0) piv = 1.0 / gd_G[k*60 + k];
        __syncthreads();
        for (int j = tid; j < 60; j += blockDim.x) gd_G[k*60 + j] *= piv;
        __syncthreads();
        if (tid < NTAIL && tid != k) fac[tid] = gd_G[tid*60 + k];
        __syncthreads();
        for (int idx = tid; idx < NTAIL*60; idx += blockDim.x) {
            int i = idx / 60, j = idx % 60;
            if (i != k) gd_G[idx] -= fac[i] * gd_G[k*60 + j];
        }
        __syncthreads();
    }
    for (int idx = tid; idx < NP*NTAIL; idx += blockDim.x) {
        int p = idx / NTAIL, n = idx % NTAIL;
        double acc = 0.0;
        for (int j = 0; j < NTAIL; j++)
            acc += gd_Phib[j*NP+p] * gd_G[j*60 + 30 + n];
        double v = gd_Dt[p] * acc;
        gd_PhibTQ[idx] = v;
        g_PhibTQ[idx] = (float)v;
    }
    __syncthreads();
    if (tid < 2*NTAIL) {
        int k = tid / NTAIL, n = tid % NTAIL;
        double acc = 0.0;
        for (int p = 0; p < NP; p++)
            acc += gd_C[k*NP+p] * gd_PhibTQ[p*NTAIL + n];
        g_M2[k*NTAIL+n] = (float)acc;
    }
    for (int idx = tid; idx < NC*NP; idx += blockDim.x)
        g_Phi[idx] = (float)gd_Phi[idx];
    if (tid < TEV) {
        double tt = -1.0 + 2.0*((double)t_eval[tid] - t0)/dtt;
        double Tm2 = 1.0, Tm1 = tt;
        g_PhiOut[0*TEV+tid] = 1.0f;
        g_PhiOut[1*TEV+tid] = (float)tt;
        #pragma unroll
        for (int n = 2; n < NC; n++) {
            double Tn = 2.0*tt*Tm1 - Tm2;
            g_PhiOut[n*TEV+tid] = (float)Tn; Tm2 = Tm1; Tm1 = Tn;
        }
    }
}

// ---------------- generic copy ---------------------------------------------
__global__ void k_copy(const float* __restrict__ src, float* __restrict__ dst, int n) {
    int i = blockIdx.x * blockDim.x + threadIdx.x;
    int stride = gridDim.x * blockDim.x;
    for (; i < n; i += stride) dst[i] = src[i];
}

__global__ void k_copy_if_done(int par) {
    if (!g_done) return;
    const float* src = g_B[par];
    float* dst = g_B[par ^ 1];
    int i = blockIdx.x * blockDim.x + threadIdx.x;
    int stride = gridDim.x * blockDim.x;
    for (; i < BSZ; i += stride) dst[i] = src[i];
}

__global__ void k_yf2(const float* __restrict__ y_init) {
    int i = blockIdx.x * blockDim.x + threadIdx.x;
    if (i < BATCH*DIM) {
        g_yf2[2*i]   = y_init[i];
        g_yf2[2*i+1] = g_fi[i];
    }
}

// ---------------- SGEMM 128x128, K-chunk 16, f32x2 accumulators -------------
// Per output element the FMA chain (ascending k) is IDENTICAL to R6; adjacent
// output columns (j, j+1) share one packed fma.rn.f32x2 (independent lanes).
// EPI 0: C = tanhf(acc + bias + t)   EPI 1: C = acc + bias
// TMODE 0: t = g_tcheb[row & 63]; TMODE 1: t = tvec[0]
template<int EPI, int TMODE, bool CHECK>
__launch_bounds__(256, 2)
__global__ void sgemm(const float* __restrict__ A, const float* __restrict__ B,
                      float* __restrict__ C, const float* __restrict__ bias,
                      const float* __restrict__ tvec, int M, int N, int K) {
    if (CHECK && g_done) return;
    __shared__ __align__(16) float As[2][16][132];   // [k][row], padded
    __shared__ __align__(16) float Bs[2][16][128];   // [k][col]
    const int tid = threadIdx.x;
    const int bm = blockIdx.y * 128, bn = blockIdx.x * 128;
    const int tx = (tid & 15) * 8, ty = (tid >> 4) * 8;
    const int NCH = K >> 4;

    unsigned long long acc2[8][4];
    #pragma unroll
    for (int i = 0; i < 8; i++)
        #pragma unroll
        for (int jp = 0; jp < 4; jp++) acc2[i][jp] = 0ull;

    float4 ra[2], rb[2];
    auto gload = [&](int c) {
        int k0 = c << 4;
        #pragma unroll
        for (int i = 0; i < 2; i++) {
            int idx = (i << 8) + tid;
            ra[i] = *(const float4*)(A + (long)(bm + (idx >> 2)) * K + k0 + ((idx & 3) << 2));
            rb[i] = *(const float4*)(B + (long)(k0 + (idx >> 5)) * N + bn + ((idx & 31) << 2));
        }
    };
    auto sstore = [&](int s) {
        #pragma unroll
        for (int i = 0; i < 2; i++) {
            int idx = (i << 8) + tid;
            int row = idx >> 2, c4 = (idx & 3) << 2;
            As[s][c4+0][row] = ra[i].x;
            As[s][c4+1][row] = ra[i].y;
            As[s][c4+2][row] = ra[i].z;
            As[s][c4+3][row] = ra[i].w;
            *(float4*)&Bs[s][idx >> 5][(idx & 31) << 2] = rb[i];
        }
    };

    gload(0);
    sstore(0);
    if (NCH > 1) gload(1);
    __syncthreads();

    for (int c = 0; c < NCH; c++) {
        int s = c & 1;
        if (c + 1 < NCH) sstore(s ^ 1);       // chunk c+1 (regs from prev iter)
        if (c + 2 < NCH) gload(c + 2);        // start next global loads early
        #pragma unroll
        for (int k = 0; k < 16; k++) {
            float4 a0 = *(const float4*)&As[s][k][ty];
            float4 a1 = *(const float4*)&As[s][k][ty+4];
            // B column pairs read directly as packed 64-bit lanes
            ulonglong2 bb0 = *(const ulonglong2*)&Bs[s][k][tx];
            ulonglong2 bb1 = *(const ulonglong2*)&Bs[s][k][tx+4];
            unsigned long long b2[4] = {bb0.x, bb0.y, bb1.x, bb1.y};
            float ar[8] = {a0.x,a0.y,a0.z,a0.w,a1.x,a1.y,a1.z,a1.w};
            #pragma unroll
            for (int i = 0; i < 8; i++) {
                unsigned long long ad = pk2(ar[i], ar[i]);
                #pragma unroll
                for (int jp = 0; jp < 4; jp++)
                    acc2[i][jp] = fma2(ad, b2[jp], acc2[i][jp]);
            }
        }
        __syncthreads();
    }

    // epilogue (same arithmetic expressions as the passing R6 kernel)
    float bv[8];
    *(float4*)&bv[0] = *(const float4*)&bias[bn + tx];
    *(float4*)&bv[4] = *(const float4*)&bias[bn + tx + 4];
    float tv1 = 0.0f;
    if (EPI == 0 && TMODE == 1) tv1 = tvec[0];
    #pragma unroll
    for (int i = 0; i < 8; i++) {
        int row = bm + ty + i;
        float a[8];
        #pragma unroll
        for (int jp = 0; jp < 4; jp++) upk2(acc2[i][jp], a[2*jp], a[2*jp+1]);
        float v[8];
        if (EPI == 0) {
            float tval = (TMODE == 0) ? g_tcheb[row & 63] : tv1;
            #pragma unroll
            for (int j = 0; j < 8; j++) v[j] = tanhf(a[j] + bv[j] + tval);
        } else {
            #pragma unroll
            for (int j = 0; j < 8; j++) v[j] = a[j] + bv[j];
        }
        *(float4*)&C[(long)row*N + bn + tx]     = *(float4*)&v[0];
        *(float4*)&C[(long)row*N + bn + tx + 4] = *(float4*)&v[4];
    }
}

// ---------------- build B_full and y_grid -----------------------------------
__global__ void k_ygrid(int par) {
    if (g_done) return;
    __shared__ float sPhi[NC][NP];
    int tid = threadIdx.x, b = blockIdx.x;
    for (int i = tid; i < NC*NP; i += blockDim.x)
        ((float*)sPhi)[i] = g_Phi[i];
    __syncthreads();
    int d = tid;
    const float* Brow = g_B[par] + (long)(b*DIM + d) * NTAIL;
    float r0 = g_yf2[(b*DIM + d)*2 + 0];
    float r1 = g_yf2[(b*DIM + d)*2 + 1];
    float c[NC];
    #pragma unroll
    for (int j = 0; j < NTAIL; j++) {
        float bj = Brow[j];
        c[j+2] = bj;
        r0 -= bj * g_PD2[j*2+0];
        r1 -= bj * g_PD2[j*2+1];
    }
    c[0] = r0 * g_inv0[0] + r1 * g_inv0[2];
    c[1] = r0 * g_inv0[1] + r1 * g_inv0[3];
    for (int p = 0; p < NP; p++) {
        float acc = 0.0f;
        #pragma unroll
        for (int n = 0; n < NC; n++) acc += c[n] * sPhi[n][p];
        g_yg[((long)b*NP + p)*DIM + d] = acc;
    }
}

// ---------------- B_new + delta partial sums --------------------------------
__global__ void k_bnew(int par) {
    if (g_done) return;
    __shared__ float sP[NP][NTAIL];
    __shared__ float sM2[2][NTAIL];
    int tid = threadIdx.x, b = blockIdx.x;
    for (int i = tid; i < NP*NTAIL; i += blockDim.x) ((float*)sP)[i] = g_PhibTQ[i];
    if (tid < 2*NTAIL) ((float*)sM2)[tid] = g_M2[tid];
    __syncthreads();
    int d = tid;
    float acc[NTAIL];
    #pragma unroll
    for (int n = 0; n < NTAIL; n++) acc[n] = 0.0f;
    for (int p = 0; p < NP; p++) {
        float v = g_f[((long)b*NP + p)*DIM + d];
        #pragma unroll
        for (int n = 0; n < NTAIL; n++) acc[n] += v * sP[p][n];
    }
    float y0 = g_yf2[(b*DIM + d)*2 + 0];
    float y1 = g_yf2[(b*DIM + d)*2 + 1];
    const float* Bp = g_B[par] + (long)(b*DIM + d) * NTAIL;
    float* Bn = g_B[par ^ 1] + (long)(b*DIM + d) * NTAIL;
    float ss = 0.0f;
    #pragma unroll
    for (int n = 0; n < NTAIL; n++) {
        float val = acc[n] - y0 * sM2[0][n] - y1 * sM2[1][n];
        Bn[n] = val;
        float df = val - Bp[n];
        ss += df * df;
    }
    #pragma unroll
    for (int o = 16; o > 0; o >>= 1) ss += __shfl_down_sync(0xffffffffu, ss, o);
    __shared__ float wsum[8];
    if ((tid & 31) == 0) wsum[tid >> 5] = ss;
    __syncthreads();
    if (tid == 0) {
        float t = 0.0f;
        #pragma unroll
        for (int w = 0; w < 8; w++) t += wsum[w];
        g_bsum[b] = t;
    }
}

__global__ void k_finalize() {
    int tid = threadIdx.x;  // 256 threads
    __shared__ float sh[256];
    if (g_done) return;
    float s = g_bsum[tid] + g_bsum[tid + 256];
    sh[tid] = s;
    __syncthreads();
    for (int o = 128; o > 0; o >>= 1) {
        if (tid < o) sh[tid] += sh[tid + o];
        __syncthreads();
    }
    if (tid == 0) {
        float d = sqrtf(sh[0]);
        g_delta = d;
        if (d < TOLF) g_done = 1;
    }
}

// ---------------- final trajectory ------------------------------------------
__global__ void k_traj(float* __restrict__ out_traj) {
    __shared__ float sPO[NC*TEV];
    int tid = threadIdx.x, b = blockIdx.x;
    for (int i = tid; i < NC*TEV; i += blockDim.x) sPO[i] = g_PhiOut[i];
    __syncthreads();
    int d = tid;
    const float* Brow = g_B[0] + (long)(b*DIM + d) * NTAIL;
    float r0 = g_yf2[(b*DIM + d)*2 + 0];
    float r1 = g_yf2[(b*DIM + d)*2 + 1];
    float c[NC];
    #pragma unroll
    for (int j = 0; j < NTAIL; j++) {
        float bj = Brow[j];
        c[j+2] = bj;
        r0 -= bj * g_PD2[j*2+0];
        r1 -= bj * g_PD2[j*2+1];
    }
    c[0] = r0 * g_inv0[0] + r1 * g_inv0[2];
    c[1] = r0 * g_inv0[1] + r1 * g_inv0[3];
    #pragma unroll
    for (int t = 0; t < TEV; t++) {
        float acc = 0.0f;
        #pragma unroll
        for (int n = 0; n < NC; n++) acc += c[n] * sPO[n*TEV + t];
        out_traj[((long)t*BATCH + b)*DIM + d] = acc;
    }
}

__global__ void k_misc(const float* __restrict__ t_eval, float* __restrict__ out, int tn) {
    int tid = threadIdx.x;
    if (tid < tn) out[tid] = t_eval[tid];
    if (tid == 31) out[DELTA_OFF] = g_delta;
}

// ---------------- launch ----------------------------------------------------
extern "C" void kernel_launch(void* const* d_in, const int* in_sizes, int n_in,
                              void* d_out, int out_size) {
    const float* y_init = (const float*)d_in[0];
    const float* t_eval = (const float*)d_in[1];
    const float* B_init = (const float*)d_in[2];
    const float* W1 = (const float*)d_in[3];
    const float* b1 = (const float*)d_in[4];
    const float* W2 = (const float*)d_in[5];
    const float* b2 = (const float*)d_in[6];
    float* out = (float*)d_out;
    int tn = in_sizes[1];

    float *pB0, *pyg, *ph, *pf, *ph0, *pfi;
    cudaGetSymbolAddress((void**)&pB0, g_B);
    cudaGetSymbolAddress((void**)&pyg, g_yg);
    cudaGetSymbolAddress((void**)&ph,  g_h);
    cudaGetSymbolAddress((void**)&pf,  g_f);
    cudaGetSymbolAddress((void**)&ph0, g_h0);
    cudaGetSymbolAddress((void**)&pfi, g_fi);

    k_precompute<<<1, 256>>>(t_eval, tn);
    k_copy<<<2048, 256>>>(B_init, pB0, BSZ);

    // f_init = vf_point(t0, y_init)
    sgemm<0, 1, false><<<dim3(HID/128, BATCH/128), 256>>>(
        y_init, W1, ph0, b1, t_eval, BATCH, HID, DIM);
    sgemm<1, 0, false><<<dim3(DIM/128, BATCH/128), 256>>>(
        ph0, W2, pfi, b2, t_eval, BATCH, DIM, HID);
    k_yf2<<<(BATCH*DIM + 255)/256, 256>>>(y_init);

    for (int it = 0; it < MAXIT; it++) {
        int par = it & 1;
        k_ygrid<<<BATCH, 256>>>(par);
        sgemm<0, 0, true><<<dim3(HID/128, MROWS/128), 256>>>(
            pyg, W1, ph, b1, t_eval, MROWS, HID, DIM);
        sgemm<1, 0, true><<<dim3(DIM/128, MROWS/128), 256>>>(
            ph, W2, pf, b2, t_eval, MROWS, DIM, HID);
        k_bnew<<<BATCH, 256>>>(par);
        k_copy_if_done<<<2048, 256>>>(par);
        k_finalize<<<1, 256>>>();
    }

    // final B lives in g_B[0] after 10 iterations
    k_traj<<<BATCH, 256>>>(out + TEV);
    k_misc<<<1, 32>>>(t_eval, out, tn);
    k_copy<<<2048, 256>>>(pB0, out + B_OFF, BSZ);
}